// round 2
// baseline (speedup 1.0000x reference)
#include <cuda_runtime.h>
#include <cuda_bf16.h>

#define BATCH   8
#define SEQ     2048
#define EMBED   1024
#define HEAD    128
#define MROWS   (BATCH * SEQ)      // 16384

// Scratch for K and V projections — __device__ globals, no alloc.
__device__ float g_Kbuf[MROWS * HEAD];
__device__ float g_Vbuf[MROWS * HEAD];

// ---------------------------------------------------------------------------
// Projection GEMM: K = x @ Wk, V = x @ Wv. Combined N=256 via blockIdx.y.
// 128x128x8 tiles, 256 threads, 8x8 register tile, double-buffered smem.
// grid = (16384/128, 2)
// ---------------------------------------------------------------------------
__global__ __launch_bounds__(256, 2) void proj_kernel(
    const float* __restrict__ x,
    const float* __restrict__ Wk,
    const float* __restrict__ Wv)
{
    __shared__ __align__(16) float As[2][8][132];   // [k][m] transposed, padded
    __shared__ __align__(16) float Bs[2][8][128];   // [k][n]

    const int bm  = blockIdx.x;
    const int bn  = blockIdx.y;
    const int tid = threadIdx.x;
    const int tx  = tid & 15;
    const int ty  = tid >> 4;
    const int am  = tid >> 1;            // A load: row within tile
    const int ak4 = (tid & 1) * 4;       // A load: k-offset
    const int bk  = tid >> 5;            // B load: k row
    const int bn4 = (tid & 31) * 4;      // B load: n-offset

    const float* W = bn ? Wv : Wk;
    const float* arow = x + (size_t)(bm * 128 + am) * EMBED;

    // preload tile 0
    float4 av = *(const float4*)&arow[ak4];
    float4 bv = *(const float4*)&W[bk * HEAD + bn4];
    As[0][ak4 + 0][am] = av.x;
    As[0][ak4 + 1][am] = av.y;
    As[0][ak4 + 2][am] = av.z;
    As[0][ak4 + 3][am] = av.w;
    *(float4*)&Bs[0][bk][bn4] = bv;
    __syncthreads();

    float acc[8][8] = {};
    int cur = 0;

    for (int k0 = 8; k0 <= EMBED; k0 += 8) {
        const bool more = (k0 < EMBED);
        if (more) {
            av = *(const float4*)&arow[k0 + ak4];
            bv = *(const float4*)&W[(k0 + bk) * HEAD + bn4];
        }
        #pragma unroll
        for (int kk = 0; kk < 8; kk++) {
            float4 a0 = *(const float4*)&As[cur][kk][ty * 4];
            float4 a1 = *(const float4*)&As[cur][kk][64 + ty * 4];
            float4 b0 = *(const float4*)&Bs[cur][kk][tx * 4];
            float4 b1 = *(const float4*)&Bs[cur][kk][64 + tx * 4];
            float a[8] = {a0.x, a0.y, a0.z, a0.w, a1.x, a1.y, a1.z, a1.w};
            float b[8] = {b0.x, b0.y, b0.z, b0.w, b1.x, b1.y, b1.z, b1.w};
            #pragma unroll
            for (int i = 0; i < 8; i++)
                #pragma unroll
                for (int j = 0; j < 8; j++)
                    acc[i][j] += a[i] * b[j];
        }
        if (more) {
            int nxt = cur ^ 1;
            As[nxt][ak4 + 0][am] = av.x;
            As[nxt][ak4 + 1][am] = av.y;
            As[nxt][ak4 + 2][am] = av.z;
            As[nxt][ak4 + 3][am] = av.w;
            *(float4*)&Bs[nxt][bk][bn4] = bv;
            __syncthreads();
            cur = nxt;
        }
    }

    float* dst = bn ? g_Vbuf : g_Kbuf;
    #pragma unroll
    for (int i = 0; i < 8; i++) {
        int r = bm * 128 + ((i < 4) ? (ty * 4 + i) : (64 + ty * 4 + i - 4));
        float4 v0 = make_float4(acc[i][0], acc[i][1], acc[i][2], acc[i][3]);
        float4 v1 = make_float4(acc[i][4], acc[i][5], acc[i][6], acc[i][7]);
        *(float4*)&dst[(size_t)r * HEAD + tx * 4]      = v0;
        *(float4*)&dst[(size_t)r * HEAD + 64 + tx * 4] = v1;
    }
}

// ---------------------------------------------------------------------------
// Flash attention (causal), fp32. Q = K (reference bug preserved).
// BQ=64 query tile per CTA, BK=64 key tiles, online softmax.
// K-tile and V-tile share one smem buffer (K for S-phase, V for PV-phase).
// smem = 84KB -> 2 CTAs/SM. 256 threads.
// ---------------------------------------------------------------------------
#define QT_S 66
#define SS_S 65

__global__ __launch_bounds__(256, 2) void attn_kernel(float* __restrict__ out)
{
    const int qi = (int)gridDim.x - 1 - (int)blockIdx.x;  // big tiles first
    const int b  = blockIdx.y;

    extern __shared__ float sm[];
    float* Qt   = sm;                 // [128][66]  transposed Q tile
    float* KV   = Qt + 128 * QT_S;    // union: Kt [128][66] / Vs [64][128] swizzled
    float* Ss   = KV + 128 * QT_S;    // [64][65]  scores / probs
    float* pm   = Ss + 64 * SS_S;     // [256] partial max / partial sum
    float* mrow = pm + 256;           // [64]
    float* lrow = mrow + 64;          // [64]
    float* srow = lrow + 64;          // [64]

    const int tid = threadIdx.x;
    const float* Kbase = g_Kbuf + (size_t)b * SEQ * HEAD;
    const float* Vbase = g_Vbuf + (size_t)b * SEQ * HEAD;

    const int lr  = tid >> 2;          // load row (0..63)
    const int ld4 = (tid & 3) * 4;     // load d-offset

    // --- load Q tile (q = key(x)) transposed ---
    {
        const float* src = &Kbase[(size_t)(qi * 64 + lr) * HEAD];
        #pragma unroll
        for (int it = 0; it < 8; it++) {
            int d = ld4 + 16 * it;
            float4 v = *(const float4*)&src[d];
            Qt[(d + 0) * QT_S + lr] = v.x;
            Qt[(d + 1) * QT_S + lr] = v.y;
            Qt[(d + 2) * QT_S + lr] = v.z;
            Qt[(d + 3) * QT_S + lr] = v.w;
        }
    }
    if (tid < 64) { mrow[tid] = -1e30f; lrow[tid] = 0.0f; }

    float O[32] = {};
    const int orow = tid >> 2;
    const int oc4  = (tid & 3) * 4;

    // S-compute warp layout: conflict-free scalar LDS
    const int w  = tid >> 5, l = tid & 31;
    const int tx = (l & 7) | ((w & 1) << 3);    // 0..15
    const int ty = (l >> 3) | ((w >> 1) << 2);  // 0..15

    // softmax layout: 4 threads per row, 16 cols each
    const int sq = tid >> 6;       // 0..3
    const int sr = tid & 63;       // row

    const float sc = 0.08838834764831845f;  // 1/sqrt(128)
    __syncthreads();

    for (int j = 0; j <= qi; j++) {
        // --- load K tile transposed into KV ---
        {
            const float* src = &Kbase[(size_t)(j * 64 + lr) * HEAD];
            #pragma unroll
            for (int it = 0; it < 8; it++) {
                int d = ld4 + 16 * it;
                float4 v = *(const float4*)&src[d];
                KV[(d + 0) * QT_S + lr] = v.x;
                KV[(d + 1) * QT_S + lr] = v.y;
                KV[(d + 2) * QT_S + lr] = v.z;
                KV[(d + 3) * QT_S + lr] = v.w;
            }
        }
        __syncthreads();

        // --- S = Q K^T ---
        float sacc[4][4] = {};
        #pragma unroll 4
        for (int d = 0; d < 128; d++) {
            float a0 = Qt[d * QT_S + ty * 4 + 0];
            float a1 = Qt[d * QT_S + ty * 4 + 1];
            float a2 = Qt[d * QT_S + ty * 4 + 2];
            float a3 = Qt[d * QT_S + ty * 4 + 3];
            float b0 = KV[d * QT_S + tx * 4 + 0];
            float b1 = KV[d * QT_S + tx * 4 + 1];
            float b2 = KV[d * QT_S + tx * 4 + 2];
            float b3 = KV[d * QT_S + tx * 4 + 3];
            sacc[0][0] += a0 * b0; sacc[0][1] += a0 * b1; sacc[0][2] += a0 * b2; sacc[0][3] += a0 * b3;
            sacc[1][0] += a1 * b0; sacc[1][1] += a1 * b1; sacc[1][2] += a1 * b2; sacc[1][3] += a1 * b3;
            sacc[2][0] += a2 * b0; sacc[2][1] += a2 * b1; sacc[2][2] += a2 * b2; sacc[2][3] += a2 * b3;
            sacc[3][0] += a3 * b0; sacc[3][1] += a3 * b1; sacc[3][2] += a3 * b2; sacc[3][3] += a3 * b3;
        }
        {
            const bool diag = (j == qi);
            #pragma unroll
            for (int i = 0; i < 4; i++) {
                int r = ty * 4 + i;
                #pragma unroll
                for (int jj = 0; jj < 4; jj++) {
                    int kc = tx * 4 + jj;
                    float v = sacc[i][jj] * sc;
                    if (diag && kc > r) v = -1e30f;
                    Ss[r * SS_S + kc] = v;
                }
            }
        }
        __syncthreads();

        // --- V load (overlapped) + softmax partial max; V overwrites Kt ---
        {
            const float* vsrc = &Vbase[(size_t)(j * 64 + lr) * HEAD];
            const int vswz = (lr & 1) << 4;
            float4 vv[4];
            #pragma unroll
            for (int it = 0; it < 4; it++)
                vv[it] = *(const float4*)&vsrc[ld4 + 16 * it];

            float pmx = -1e30f;
            #pragma unroll
            for (int c = 0; c < 16; c++)
                pmx = fmaxf(pmx, Ss[sr * SS_S + sq * 16 + c]);
            pm[tid] = pmx;

            #pragma unroll
            for (int it = 0; it < 4; it++)
                *(float4*)&KV[lr * 128 + ((ld4 + 16 * it) ^ vswz)] = vv[it];
            #pragma unroll
            for (int it = 4; it < 8; it++) {
                float4 v = *(const float4*)&vsrc[ld4 + 16 * it];
                *(float4*)&KV[lr * 128 + ((ld4 + 16 * it) ^ vswz)] = v;
            }
        }
        __syncthreads();

        // --- combine row max, compute rescale ---
        if (tid < 64) {
            float mx = fmaxf(fmaxf(pm[tid], pm[64 + tid]),
                             fmaxf(pm[128 + tid], pm[192 + tid]));
            float m_old = mrow[tid];
            mx = fmaxf(mx, m_old);
            srow[tid] = __expf(m_old - mx);
            mrow[tid] = mx;
        }
        __syncthreads();

        // --- exp pass (partial sums) + O rescale ---
        {
            float mx  = mrow[sr];
            float sum = 0.0f;
            #pragma unroll
            for (int c = 0; c < 16; c++) {
                float p = __expf(Ss[sr * SS_S + sq * 16 + c] - mx);
                Ss[sr * SS_S + sq * 16 + c] = p;
                sum += p;
            }
            pm[tid] = sum;
            float s = srow[orow];
            #pragma unroll
            for (int u = 0; u < 32; u++) O[u] *= s;
        }
        __syncthreads();

        if (tid < 64)
            lrow[tid] = lrow[tid] * srow[tid] +
                        pm[tid] + pm[64 + tid] + pm[128 + tid] + pm[192 + tid];

        // --- O += P @ V ---
        {
            const float* Prow = &Ss[orow * SS_S];
            #pragma unroll 2
            for (int k = 0; k < 64; k++) {
                const float p  = Prow[k];
                const int   kx = k & 1;
                const float* vr = &KV[k * 128];
                #pragma unroll
                for (int jj = 0; jj < 8; jj++) {
                    float4 v = *(const float4*)&vr[oc4 + 16 * (jj ^ kx)];
                    O[jj * 4 + 0] += p * v.x;
                    O[jj * 4 + 1] += p * v.y;
                    O[jj * 4 + 2] += p * v.z;
                    O[jj * 4 + 3] += p * v.w;
                }
            }
        }
        __syncthreads();
    }

    // --- finalize ---
    const float inv_l = 1.0f / lrow[orow];
    float* op = out + ((size_t)b * SEQ + qi * 64 + orow) * HEAD;
    #pragma unroll
    for (int jj = 0; jj < 8; jj++) {
        float4 v = make_float4(O[jj * 4 + 0] * inv_l, O[jj * 4 + 1] * inv_l,
                               O[jj * 4 + 2] * inv_l, O[jj * 4 + 3] * inv_l);
        *(float4*)&op[oc4 + 16 * jj] = v;
    }
}

// ---------------------------------------------------------------------------
extern "C" void kernel_launch(void* const* d_in, const int* in_sizes, int n_in,
                              void* d_out, int out_size)
{
    const float* x  = (const float*)d_in[0];
    const float* Wk = (const float*)d_in[1];
    // d_in[2] = W_query: unused (reference uses key() for q too)
    const float* Wv = (const float*)d_in[3];
    float* out = (float*)d_out;

    dim3 pgrid(MROWS / 128, 2);
    proj_kernel<<<pgrid, 256>>>(x, Wk, Wv);

    const int smem_bytes = (128 * QT_S * 2 + 64 * SS_S + 256 + 3 * 64) * (int)sizeof(float);
    cudaFuncSetAttribute(attn_kernel, cudaFuncAttributeMaxDynamicSharedMemorySize, smem_bytes);

    dim3 agrid(SEQ / 64, BATCH);
    attn_kernel<<<agrid, 256, smem_bytes>>>(out);
}

// round 4
// speedup vs baseline: 2.4236x; 2.4236x over previous
#include <cuda_runtime.h>
#include <cuda_bf16.h>

#define BATCH   8
#define SEQ     2048
#define EMBED   1024
#define HEAD    128
#define MROWS   (BATCH * SEQ)      // 16384
#define TQ      16                 // q-tiles per batch (128 rows each)
#define ASTR    132                // smem stride (floats) for Q/KV tiles
#define SSTR    132                // smem stride for S tile (128 cols + pad)

// Scratch — __device__ globals, no alloc.
__device__ float g_Kbuf[MROWS * HEAD];
__device__ float g_Vbuf[MROWS * HEAD];
__device__ float g_pO[2 * MROWS * HEAD];   // split-K partial O~ (unnormalized)
__device__ float g_pm[2 * MROWS];          // partial row max
__device__ float g_pl[2 * MROWS];          // partial row sum

// ---------------------------------------------------------------------------
// Projection GEMM: K = x @ Wk, V = x @ Wv (measured ~at fp32 peak).
// ---------------------------------------------------------------------------
__global__ __launch_bounds__(256, 2) void proj_kernel(
    const float* __restrict__ x,
    const float* __restrict__ Wk,
    const float* __restrict__ Wv)
{
    __shared__ __align__(16) float As[2][8][132];
    __shared__ __align__(16) float Bs[2][8][128];

    const int bm  = blockIdx.x;
    const int bn  = blockIdx.y;
    const int tid = threadIdx.x;
    const int tx  = tid & 15;
    const int ty  = tid >> 4;
    const int am  = tid >> 1;
    const int ak4 = (tid & 1) * 4;
    const int bk  = tid >> 5;
    const int bn4 = (tid & 31) * 4;

    const float* W = bn ? Wv : Wk;
    const float* arow = x + (size_t)(bm * 128 + am) * EMBED;

    float4 av = *(const float4*)&arow[ak4];
    float4 bv = *(const float4*)&W[bk * HEAD + bn4];
    As[0][ak4 + 0][am] = av.x;
    As[0][ak4 + 1][am] = av.y;
    As[0][ak4 + 2][am] = av.z;
    As[0][ak4 + 3][am] = av.w;
    *(float4*)&Bs[0][bk][bn4] = bv;
    __syncthreads();

    float acc[8][8] = {};
    int cur = 0;

    for (int k0 = 8; k0 <= EMBED; k0 += 8) {
        const bool more = (k0 < EMBED);
        if (more) {
            av = *(const float4*)&arow[k0 + ak4];
            bv = *(const float4*)&W[(k0 + bk) * HEAD + bn4];
        }
        #pragma unroll
        for (int kk = 0; kk < 8; kk++) {
            float4 a0 = *(const float4*)&As[cur][kk][ty * 4];
            float4 a1 = *(const float4*)&As[cur][kk][64 + ty * 4];
            float4 b0 = *(const float4*)&Bs[cur][kk][tx * 4];
            float4 b1 = *(const float4*)&Bs[cur][kk][64 + tx * 4];
            float a[8] = {a0.x, a0.y, a0.z, a0.w, a1.x, a1.y, a1.z, a1.w};
            float b[8] = {b0.x, b0.y, b0.z, b0.w, b1.x, b1.y, b1.z, b1.w};
            #pragma unroll
            for (int i = 0; i < 8; i++)
                #pragma unroll
                for (int j = 0; j < 8; j++)
                    acc[i][j] += a[i] * b[j];
        }
        if (more) {
            int nxt = cur ^ 1;
            As[nxt][ak4 + 0][am] = av.x;
            As[nxt][ak4 + 1][am] = av.y;
            As[nxt][ak4 + 2][am] = av.z;
            As[nxt][ak4 + 3][am] = av.w;
            *(float4*)&Bs[nxt][bk][bn4] = bv;
            __syncthreads();
            cur = nxt;
        }
    }

    float* dst = bn ? g_Vbuf : g_Kbuf;
    #pragma unroll
    for (int i = 0; i < 8; i++) {
        int r = bm * 128 + ((i < 4) ? (ty * 4 + i) : (64 + ty * 4 + i - 4));
        float4 v0 = make_float4(acc[i][0], acc[i][1], acc[i][2], acc[i][3]);
        float4 v1 = make_float4(acc[i][4], acc[i][5], acc[i][6], acc[i][7]);
        *(float4*)&dst[(size_t)r * HEAD + tx * 4]      = v0;
        *(float4*)&dst[(size_t)r * HEAD + 64 + tx * 4] = v1;
    }
}

// ---------------------------------------------------------------------------
// Flash-attention partial (split-K over key tiles, causal, q = key(x)).
// BQ=BK=128, 256 threads, 8x8 regtile (strided ownership).
// grid = 256 1-D blocks: decode (qi, b, half), big qi first.
// ---------------------------------------------------------------------------
__global__ __launch_bounds__(256, 1) void attn_partial(void)
{
    const int t    = blockIdx.x;
    const int qi   = (TQ - 1) - (t >> 4);     // big tiles first
    const int b    = (t >> 1) & 7;
    const int half = t & 1;
    const int h    = (qi + 1) >> 1;
    const int jbeg = half ? h : 0;
    const int jend = half ? (qi + 1) : h;

    const int tid = threadIdx.x;
    const int w   = tid >> 5;
    const int l   = tid & 31;

    const size_t prow0 = (size_t)half * MROWS + (size_t)b * SEQ + qi * 128;
    const size_t pbase = prow0 * HEAD;

    if (jbeg == jend) {   // empty half (qi==0, half==0): zero partial
        float4 z = make_float4(0.f, 0.f, 0.f, 0.f);
        #pragma unroll
        for (int i = 0; i < 16; i++)
            *(float4*)&g_pO[pbase + (size_t)(w * 16 + i) * HEAD + l * 4] = z;
        if (tid < 128) { g_pm[prow0 + tid] = -1e30f; g_pl[prow0 + tid] = 0.0f; }
        return;
    }

    extern __shared__ float sm[];
    float* Qs   = sm;                    // [128][ASTR]
    float* KVs  = Qs + 128 * ASTR;       // [128][ASTR]  (K tile, then V tile)
    float* Ss   = KVs + 128 * ASTR;      // [128][SSTR]
    float* mrow = Ss + 128 * SSTR;       // [128]
    float* lrow = mrow + 128;            // [128]
    float* srow = lrow + 128;            // [128]

    const float* Kbase = g_Kbuf + (size_t)b * SEQ * HEAD;
    const float* Vbase = g_Vbuf + (size_t)b * SEQ * HEAD;

    // --- load Q tile (row-major; warp = one 512B row per iteration) ---
    {
        const float* src = Kbase + (size_t)(qi * 128) * HEAD;
        #pragma unroll
        for (int i = 0; i < 16; i++) {
            int r = w * 16 + i;
            *(float4*)&Qs[r * ASTR + l * 4] = *(const float4*)&src[(size_t)r * HEAD + l * 4];
        }
    }
    if (tid < 128) { mrow[tid] = -1e30f; lrow[tid] = 0.0f; }

    const int tx = tid & 15;     // owns cols {tx + 16*jj}
    const int ty = tid >> 4;     // owns rows {ty + 16*ii}
    const int sr = tid >> 1;     // softmax row
    const int sh = tid & 1;      // softmax half (64 cols)

    float O[8][8] = {};
    const float sc = 0.08838834764831845f;   // 1/sqrt(128)

    __syncthreads();

    for (int j = jbeg; j < jend; j++) {
        // --- load K tile ---
        {
            const float* src = Kbase + (size_t)(j * 128) * HEAD;
            #pragma unroll
            for (int i = 0; i < 16; i++) {
                int r = w * 16 + i;
                *(float4*)&KVs[r * ASTR + l * 4] = *(const float4*)&src[(size_t)r * HEAD + l * 4];
            }
        }
        __syncthreads();

        // --- S = Q K^T : 8x8 per thread, vec4 along d ---
        float sacc[8][8] = {};
        #pragma unroll 1
        for (int d4 = 0; d4 < 32; d4++) {
            float4 qv[8];
            #pragma unroll
            for (int ii = 0; ii < 8; ii++)
                qv[ii] = *(const float4*)&Qs[(ty + 16 * ii) * ASTR + d4 * 4];
            #pragma unroll
            for (int jh = 0; jh < 2; jh++) {
                float4 kv[4];
                #pragma unroll
                for (int jx = 0; jx < 4; jx++)
                    kv[jx] = *(const float4*)&KVs[(tx + 16 * (jh * 4 + jx)) * ASTR + d4 * 4];
                #pragma unroll
                for (int ii = 0; ii < 8; ii++)
                    #pragma unroll
                    for (int jx = 0; jx < 4; jx++) {
                        int jj = jh * 4 + jx;
                        sacc[ii][jj] += qv[ii].x * kv[jx].x + qv[ii].y * kv[jx].y
                                      + qv[ii].z * kv[jx].z + qv[ii].w * kv[jx].w;
                    }
            }
        }
        // scale + causal mask + store S
        {
            const bool diag = (j == qi);
            #pragma unroll
            for (int ii = 0; ii < 8; ii++) {
                int r = ty + 16 * ii;
                #pragma unroll
                for (int jj = 0; jj < 8; jj++) {
                    int c = tx + 16 * jj;
                    float v = sacc[ii][jj] * sc;
                    if (diag && c > r) v = -1e30f;
                    Ss[r * SSTR + c] = v;
                }
            }
        }
        __syncthreads();

        // --- V copy (overlapped) + warp-sync softmax update ---
        {
            const float* vsrc = Vbase + (size_t)(j * 128) * HEAD;
            float4 vb[8];
            #pragma unroll
            for (int i = 0; i < 8; i++)
                vb[i] = *(const float4*)&vsrc[(size_t)(w * 16 + i) * HEAD + l * 4];

            // row max over my 64 cols
            const float* srp = &Ss[sr * SSTR + sh * 64];
            float mx = -1e30f;
            #pragma unroll 16
            for (int c = 0; c < 64; c++) mx = fmaxf(mx, srp[c]);
            mx = fmaxf(mx, __shfl_xor_sync(0xFFFFFFFFu, mx, 1));
            float m_old = mrow[sr];
            mx = fmaxf(mx, m_old);

            #pragma unroll
            for (int i = 0; i < 8; i++)
                *(float4*)&KVs[(w * 16 + i) * ASTR + l * 4] = vb[i];
            #pragma unroll
            for (int i = 8; i < 16; i++) {
                float4 v = *(const float4*)&vsrc[(size_t)(w * 16 + i) * HEAD + l * 4];
                *(float4*)&KVs[(w * 16 + i) * ASTR + l * 4] = v;
            }

            float sum = 0.0f;
            float* swp = &Ss[sr * SSTR + sh * 64];
            #pragma unroll 16
            for (int c = 0; c < 64; c++) {
                float p = __expf(swp[c] - mx);
                swp[c] = p;
                sum += p;
            }
            sum += __shfl_xor_sync(0xFFFFFFFFu, sum, 1);
            if (sh == 0) {
                float scale = __expf(m_old - mx);
                srow[sr] = scale;
                mrow[sr] = mx;
                lrow[sr] = lrow[sr] * scale + sum;
            }
        }
        __syncthreads();

        // --- O = O*scale + P @ V ---
        {
            float s_[8];
            #pragma unroll
            for (int ii = 0; ii < 8; ii++) s_[ii] = srow[ty + 16 * ii];
            #pragma unroll
            for (int ii = 0; ii < 8; ii++)
                #pragma unroll
                for (int jj = 0; jj < 8; jj++) O[ii][jj] *= s_[ii];

            #pragma unroll 1
            for (int k0 = 0; k0 < 128; k0 += 4) {
                float4 pv[8];
                #pragma unroll
                for (int ii = 0; ii < 8; ii++)
                    pv[ii] = *(const float4*)&Ss[(ty + 16 * ii) * SSTR + k0];
                #pragma unroll
                for (int kk = 0; kk < 4; kk++) {
                    float vk[8];
                    #pragma unroll
                    for (int jj = 0; jj < 8; jj++)
                        vk[jj] = KVs[(k0 + kk) * ASTR + tx + 16 * jj];
                    #pragma unroll
                    for (int ii = 0; ii < 8; ii++) {
                        float p = (kk == 0) ? pv[ii].x : (kk == 1) ? pv[ii].y
                                : (kk == 2) ? pv[ii].z : pv[ii].w;
                        #pragma unroll
                        for (int jj = 0; jj < 8; jj++)
                            O[ii][jj] += p * vk[jj];
                    }
                }
            }
        }
        __syncthreads();   // protect KVs before next K load
    }

    // --- write partials (unnormalized O~, m, l) ---
    #pragma unroll
    for (int ii = 0; ii < 8; ii++) {
        int r = ty + 16 * ii;
        #pragma unroll
        for (int jj = 0; jj < 8; jj++)
            g_pO[pbase + (size_t)r * HEAD + tx + 16 * jj] = O[ii][jj];
    }
    if (tid < 128) {
        g_pm[prow0 + tid] = mrow[tid];
        g_pl[prow0 + tid] = lrow[tid];
    }
}

// ---------------------------------------------------------------------------
// Merge the two split-K partials.
// ---------------------------------------------------------------------------
__global__ __launch_bounds__(256) void merge_kernel(float* __restrict__ out)
{
    const int idx = blockIdx.x * 256 + threadIdx.x;   // 0 .. MROWS*32-1
    const int row = idx >> 5;
    const int c4  = idx & 31;

    const float m0 = g_pm[row], m1 = g_pm[MROWS + row];
    const float l0 = g_pl[row], l1 = g_pl[MROWS + row];
    const float m  = fmaxf(m0, m1);
    const float a0 = __expf(m0 - m);
    const float a1 = __expf(m1 - m);
    const float inv = 1.0f / (a0 * l0 + a1 * l1);

    float4 o0 = *(const float4*)&g_pO[(size_t)row * HEAD + c4 * 4];
    float4 o1 = *(const float4*)&g_pO[(size_t)(MROWS + row) * HEAD + c4 * 4];
    float4 r;
    r.x = (a0 * o0.x + a1 * o1.x) * inv;
    r.y = (a0 * o0.y + a1 * o1.y) * inv;
    r.z = (a0 * o0.z + a1 * o1.z) * inv;
    r.w = (a0 * o0.w + a1 * o1.w) * inv;
    *(float4*)&out[(size_t)row * HEAD + c4 * 4] = r;
}

// ---------------------------------------------------------------------------
extern "C" void kernel_launch(void* const* d_in, const int* in_sizes, int n_in,
                              void* d_out, int out_size)
{
    const float* x  = (const float*)d_in[0];
    const float* Wk = (const float*)d_in[1];
    // d_in[2] = W_query: unused (reference uses key() for q too)
    const float* Wv = (const float*)d_in[3];
    float* out = (float*)d_out;

    dim3 pgrid(MROWS / 128, 2);
    proj_kernel<<<pgrid, 256>>>(x, Wk, Wv);

    const int smem_bytes = (128 * ASTR * 2 + 128 * SSTR + 3 * 128) * (int)sizeof(float);
    cudaFuncSetAttribute(attn_partial, cudaFuncAttributeMaxDynamicSharedMemorySize, smem_bytes);
    attn_partial<<<256, 256, smem_bytes>>>();

    merge_kernel<<<(MROWS * 32) / 256, 256>>>(out);
}

// round 7
// speedup vs baseline: 2.8081x; 1.1586x over previous
#include <cuda_runtime.h>
#include <cuda_bf16.h>
#include <stdint.h>

#define BATCH   8
#define SEQ     2048
#define EMBED   1024
#define HEAD    128
#define MROWS   16384
#define TQ      16
#define ASTR    132
#define SSTR    132

// Scratch — __device__ globals, no alloc.
__device__ float g_Kbuf[MROWS * HEAD];
__device__ float g_Vbuf[MROWS * HEAD];
__device__ float g_pO[2 * MROWS * HEAD];
__device__ float g_pm[2 * MROWS];
__device__ float g_pl[2 * MROWS];
// W transposed + bf16-split: [(m*128+n)][k]  (m: 0=K, 1=V)
__device__ __align__(16) __nv_bfloat16 g_wt_hi[2 * HEAD * EMBED];
__device__ __align__(16) __nv_bfloat16 g_wt_lo[2 * HEAD * EMBED];

// ---------------------------------------------------------------------------
__device__ __forceinline__ uint32_t smem_u32(const void* p) {
    uint32_t a;
    asm("{ .reg .u64 t; cvta.to.shared.u64 t, %1; cvt.u32.u64 %0, t; }"
        : "=r"(a) : "l"(p));
    return a;
}
__device__ __forceinline__ void ldsm_x4(uint32_t* r, uint32_t addr) {
    asm volatile("ldmatrix.sync.aligned.m8n8.x4.shared.b16 {%0,%1,%2,%3}, [%4];"
                 : "=r"(r[0]), "=r"(r[1]), "=r"(r[2]), "=r"(r[3]) : "r"(addr));
}
__device__ __forceinline__ void ldsm_x2(uint32_t* r, uint32_t addr) {
    asm volatile("ldmatrix.sync.aligned.m8n8.x2.shared.b16 {%0,%1}, [%2];"
                 : "=r"(r[0]), "=r"(r[1]) : "r"(addr));
}
__device__ __forceinline__ void mma_bf16(float* c, const uint32_t* a, const uint32_t* b) {
    asm volatile(
        "mma.sync.aligned.m16n8k16.row.col.f32.bf16.bf16.f32 "
        "{%0,%1,%2,%3}, {%4,%5,%6,%7}, {%8,%9}, {%0,%1,%2,%3};"
        : "+f"(c[0]), "+f"(c[1]), "+f"(c[2]), "+f"(c[3])
        : "r"(a[0]), "r"(a[1]), "r"(a[2]), "r"(a[3]), "r"(b[0]), "r"(b[1]));
}
__device__ __forceinline__ void split2(float a, float b, uint32_t& hi, uint32_t& lo) {
    __nv_bfloat162 h = __floats2bfloat162_rn(a, b);
    float2 hf = __bfloat1622float2(h);
    __nv_bfloat162 l = __floats2bfloat162_rn(a - hf.x, b - hf.y);
    hi = *(uint32_t*)&h;
    lo = *(uint32_t*)&l;
}

// ---------------------------------------------------------------------------
// W prep: transpose + bf16-split. Wk/Wv are [1024][128].
// ---------------------------------------------------------------------------
__global__ __launch_bounds__(256) void wprep_kernel(
    const float* __restrict__ Wk, const float* __restrict__ Wv)
{
    int idx = blockIdx.x * 256 + threadIdx.x;   // 0..262143
    int n = idx & 127;
    int k = (idx >> 7) & 1023;
    int m = idx >> 17;
    float f = (m ? Wv : Wk)[k * HEAD + n];
    __nv_bfloat16 hi = __float2bfloat16(f);
    float rem = f - __bfloat162float(hi);
    __nv_bfloat16 lo = __float2bfloat16(rem);
    size_t o = (size_t)(m * HEAD + n) * EMBED + k;
    g_wt_hi[o] = hi;
    g_wt_lo[o] = lo;
}

// ---------------------------------------------------------------------------
// Projection GEMM via mma.sync bf16 (3-product split).
// CTA tile 128x128, 8 warps (2x4), warp tile 64x32, k chunked by 64.
// smem: A_hi/A_lo/B_hi/B_lo each [128][72] bf16 (stride 144B, ldmatrix
// conflict-free). grid (128, 2).
// ---------------------------------------------------------------------------
#define PSTR 72                                   // bf16 stride
#define TILE_B (128 * PSTR * 2)                   // 18432 bytes per tile
#define PROJ_SMEM (4 * TILE_B)                    // 73728

__global__ __launch_bounds__(256) void proj_mma_kernel(const float* __restrict__ x)
{
    extern __shared__ char smem[];
    __nv_bfloat16* Ahi = (__nv_bfloat16*)(smem);
    __nv_bfloat16* Alo = (__nv_bfloat16*)(smem + TILE_B);
    __nv_bfloat16* Bhi = (__nv_bfloat16*)(smem + 2 * TILE_B);
    __nv_bfloat16* Blo = (__nv_bfloat16*)(smem + 3 * TILE_B);
    const uint32_t sAhi = smem_u32(Ahi), sAlo = smem_u32(Alo);
    const uint32_t sBhi = smem_u32(Bhi), sBlo = smem_u32(Blo);

    const int bm  = blockIdx.x;
    const int bn  = blockIdx.y;
    const int tid = threadIdx.x;
    const int wid = tid >> 5;
    const int lane = tid & 31;

    const int warp_m = (wid >> 2) * 64;
    const int warp_n = (wid & 3) * 32;

    // loader mapping: row r (0..127), half h
    const int r = tid >> 1;
    const int h = tid & 1;
    const float* xrow = x + (size_t)(bm * 128 + r) * EMBED;
    const __nv_bfloat16* wh = g_wt_hi + (size_t)(bn * 128 + r) * EMBED;
    const __nv_bfloat16* wl = g_wt_lo + (size_t)(bn * 128 + r) * EMBED;

    // ldmatrix lane addresses (element offsets precomputed per lane)
    const int lg = lane >> 3, lr = lane & 7;
    // A: row = mbase + lr + (lg&1)*8 ; col = kk + (lg>>1)*8
    const int a_row_off = lr + (lg & 1) * 8;
    const int a_col_off = (lg >> 1) * 8;
    // B (x2, lanes 0-15): row = nbase + lr ; col = kk + (lg&1)*8
    const int b_lane = lane & 15;
    const int b_row_off = b_lane & 7;
    const int b_col_off = (b_lane >> 3) * 8;

    float acc[4][4][4] = {};

    for (int c = 0; c < 16; c++) {
        const int k0 = c * 64;
        __syncthreads();   // protect smem from previous iteration's readers
        // --- A: load fp32, split, store ---
        #pragma unroll
        for (int j = 0; j < 8; j++) {
            float4 f = *(const float4*)&xrow[k0 + h * 32 + j * 4];
            uint2 hi2, lo2;
            split2(f.x, f.y, hi2.x, lo2.x);
            split2(f.z, f.w, hi2.y, lo2.y);
            int off = r * PSTR + h * 32 + j * 4;
            *(uint2*)&Ahi[off] = hi2;
            *(uint2*)&Alo[off] = lo2;
        }
        // --- B: copy pre-split bf16 ---
        #pragma unroll
        for (int j = 0; j < 4; j++) {
            int ks = k0 + h * 32 + j * 8;
            int off = r * PSTR + h * 32 + j * 8;
            *(uint4*)&Bhi[off] = *(const uint4*)&wh[ks];
            *(uint4*)&Blo[off] = *(const uint4*)&wl[ks];
        }
        __syncthreads();

        // --- MMA over this 64-wide chunk ---
        #pragma unroll
        for (int kk4 = 0; kk4 < 4; kk4++) {
            const int kk = kk4 * 16;
            uint32_t ah[4][4], al[4][4], bh[4][2], bl[4][2];
            #pragma unroll
            for (int mf = 0; mf < 4; mf++) {
                uint32_t eo = (uint32_t)((warp_m + mf * 16 + a_row_off) * PSTR
                                         + kk + a_col_off) * 2;
                ldsm_x4(ah[mf], sAhi + eo);
                ldsm_x4(al[mf], sAlo + eo);
            }
            #pragma unroll
            for (int nf = 0; nf < 4; nf++) {
                uint32_t eo = (uint32_t)((warp_n + nf * 8 + b_row_off) * PSTR
                                         + kk + b_col_off) * 2;
                ldsm_x2(bh[nf], sBhi + eo);
                ldsm_x2(bl[nf], sBlo + eo);
            }
            #pragma unroll
            for (int mf = 0; mf < 4; mf++)
                #pragma unroll
                for (int nf = 0; nf < 4; nf++) {
                    mma_bf16(acc[mf][nf], ah[mf], bh[nf]);
                    mma_bf16(acc[mf][nf], ah[mf], bl[nf]);
                    mma_bf16(acc[mf][nf], al[mf], bh[nf]);
                }
        }
    }

    // --- epilogue: fragment -> gmem fp32 ---
    float* dst = (bn ? g_Vbuf : g_Kbuf) + (size_t)bm * 128 * HEAD;
    const int frow = lane >> 2;
    const int fcol = (lane & 3) * 2;
    #pragma unroll
    for (int mf = 0; mf < 4; mf++) {
        #pragma unroll
        for (int nf = 0; nf < 4; nf++) {
            int row0 = warp_m + mf * 16 + frow;
            int col  = warp_n + nf * 8 + fcol;
            *(float2*)&dst[(size_t)row0 * HEAD + col] =
                make_float2(acc[mf][nf][0], acc[mf][nf][1]);
            *(float2*)&dst[(size_t)(row0 + 8) * HEAD + col] =
                make_float2(acc[mf][nf][2], acc[mf][nf][3]);
        }
    }
}

// ---------------------------------------------------------------------------
// Flash-attention partial (unchanged from R4 — at fp32 FFMA roofline).
// ---------------------------------------------------------------------------
__global__ __launch_bounds__(256, 1) void attn_partial(void)
{
    const int t    = blockIdx.x;
    const int qi   = (TQ - 1) - (t >> 4);
    const int b    = (t >> 1) & 7;
    const int half = t & 1;
    const int h    = (qi + 1) >> 1;
    const int jbeg = half ? h : 0;
    const int jend = half ? (qi + 1) : h;

    const int tid = threadIdx.x;
    const int w   = tid >> 5;
    const int l   = tid & 31;

    const size_t prow0 = (size_t)half * MROWS + (size_t)b * SEQ + qi * 128;
    const size_t pbase = prow0 * HEAD;

    if (jbeg == jend) {
        float4 z = make_float4(0.f, 0.f, 0.f, 0.f);
        #pragma unroll
        for (int i = 0; i < 16; i++)
            *(float4*)&g_pO[pbase + (size_t)(w * 16 + i) * HEAD + l * 4] = z;
        if (tid < 128) { g_pm[prow0 + tid] = -1e30f; g_pl[prow0 + tid] = 0.0f; }
        return;
    }

    extern __shared__ float sm[];
    float* Qs   = sm;
    float* KVs  = Qs + 128 * ASTR;
    float* Ss   = KVs + 128 * ASTR;
    float* mrow = Ss + 128 * SSTR;
    float* lrow = mrow + 128;
    float* srow = lrow + 128;

    const float* Kbase = g_Kbuf + (size_t)b * SEQ * HEAD;
    const float* Vbase = g_Vbuf + (size_t)b * SEQ * HEAD;

    {
        const float* src = Kbase + (size_t)(qi * 128) * HEAD;
        #pragma unroll
        for (int i = 0; i < 16; i++) {
            int r = w * 16 + i;
            *(float4*)&Qs[r * ASTR + l * 4] = *(const float4*)&src[(size_t)r * HEAD + l * 4];
        }
    }
    if (tid < 128) { mrow[tid] = -1e30f; lrow[tid] = 0.0f; }

    const int tx = tid & 15;
    const int ty = tid >> 4;
    const int sr = tid >> 1;
    const int sh = tid & 1;

    float O[8][8] = {};
    const float sc = 0.08838834764831845f;

    __syncthreads();

    for (int j = jbeg; j < jend; j++) {
        {
            const float* src = Kbase + (size_t)(j * 128) * HEAD;
            #pragma unroll
            for (int i = 0; i < 16; i++) {
                int r = w * 16 + i;
                *(float4*)&KVs[r * ASTR + l * 4] = *(const float4*)&src[(size_t)r * HEAD + l * 4];
            }
        }
        __syncthreads();

        float sacc[8][8] = {};
        #pragma unroll 1
        for (int d4 = 0; d4 < 32; d4++) {
            float4 qv[8];
            #pragma unroll
            for (int ii = 0; ii < 8; ii++)
                qv[ii] = *(const float4*)&Qs[(ty + 16 * ii) * ASTR + d4 * 4];
            #pragma unroll
            for (int jh = 0; jh < 2; jh++) {
                float4 kv[4];
                #pragma unroll
                for (int jx = 0; jx < 4; jx++)
                    kv[jx] = *(const float4*)&KVs[(tx + 16 * (jh * 4 + jx)) * ASTR + d4 * 4];
                #pragma unroll
                for (int ii = 0; ii < 8; ii++)
                    #pragma unroll
                    for (int jx = 0; jx < 4; jx++) {
                        int jj = jh * 4 + jx;
                        sacc[ii][jj] += qv[ii].x * kv[jx].x + qv[ii].y * kv[jx].y
                                      + qv[ii].z * kv[jx].z + qv[ii].w * kv[jx].w;
                    }
            }
        }
        {
            const bool diag = (j == qi);
            #pragma unroll
            for (int ii = 0; ii < 8; ii++) {
                int r = ty + 16 * ii;
                #pragma unroll
                for (int jj = 0; jj < 8; jj++) {
                    int c = tx + 16 * jj;
                    float v = sacc[ii][jj] * sc;
                    if (diag && c > r) v = -1e30f;
                    Ss[r * SSTR + c] = v;
                }
            }
        }
        __syncthreads();

        {
            const float* vsrc = Vbase + (size_t)(j * 128) * HEAD;
            float4 vb[8];
            #pragma unroll
            for (int i = 0; i < 8; i++)
                vb[i] = *(const float4*)&vsrc[(size_t)(w * 16 + i) * HEAD + l * 4];

            const float* srp = &Ss[sr * SSTR + sh * 64];
            float mx = -1e30f;
            #pragma unroll 16
            for (int c = 0; c < 64; c++) mx = fmaxf(mx, srp[c]);
            mx = fmaxf(mx, __shfl_xor_sync(0xFFFFFFFFu, mx, 1));
            float m_old = mrow[sr];
            mx = fmaxf(mx, m_old);

            #pragma unroll
            for (int i = 0; i < 8; i++)
                *(float4*)&KVs[(w * 16 + i) * ASTR + l * 4] = vb[i];
            #pragma unroll
            for (int i = 8; i < 16; i++) {
                float4 v = *(const float4*)&vsrc[(size_t)(w * 16 + i) * HEAD + l * 4];
                *(float4*)&KVs[(w * 16 + i) * ASTR + l * 4] = v;
            }

            float sum = 0.0f;
            float* swp = &Ss[sr * SSTR + sh * 64];
            #pragma unroll 16
            for (int c = 0; c < 64; c++) {
                float p = __expf(swp[c] - mx);
                swp[c] = p;
                sum += p;
            }
            sum += __shfl_xor_sync(0xFFFFFFFFu, sum, 1);
            if (sh == 0) {
                float scale = __expf(m_old - mx);
                srow[sr] = scale;
                mrow[sr] = mx;
                lrow[sr] = lrow[sr] * scale + sum;
            }
        }
        __syncthreads();

        {
            float s_[8];
            #pragma unroll
            for (int ii = 0; ii < 8; ii++) s_[ii] = srow[ty + 16 * ii];
            #pragma unroll
            for (int ii = 0; ii < 8; ii++)
                #pragma unroll
                for (int jj = 0; jj < 8; jj++) O[ii][jj] *= s_[ii];

            #pragma unroll 1
            for (int k0 = 0; k0 < 128; k0 += 4) {
                float4 pv[8];
                #pragma unroll
                for (int ii = 0; ii < 8; ii++)
                    pv[ii] = *(const float4*)&Ss[(ty + 16 * ii) * SSTR + k0];
                #pragma unroll
                for (int kk = 0; kk < 4; kk++) {
                    float vk[8];
                    #pragma unroll
                    for (int jj = 0; jj < 8; jj++)
                        vk[jj] = KVs[(k0 + kk) * ASTR + tx + 16 * jj];
                    #pragma unroll
                    for (int ii = 0; ii < 8; ii++) {
                        float p = (kk == 0) ? pv[ii].x : (kk == 1) ? pv[ii].y
                                : (kk == 2) ? pv[ii].z : pv[ii].w;
                        #pragma unroll
                        for (int jj = 0; jj < 8; jj++)
                            O[ii][jj] += p * vk[jj];
                    }
                }
            }
        }
        __syncthreads();
    }

    #pragma unroll
    for (int ii = 0; ii < 8; ii++) {
        int r = ty + 16 * ii;
        #pragma unroll
        for (int jj = 0; jj < 8; jj++)
            g_pO[pbase + (size_t)r * HEAD + tx + 16 * jj] = O[ii][jj];
    }
    if (tid < 128) {
        g_pm[prow0 + tid] = mrow[tid];
        g_pl[prow0 + tid] = lrow[tid];
    }
}

// ---------------------------------------------------------------------------
__global__ __launch_bounds__(256) void merge_kernel(float* __restrict__ out)
{
    const int idx = blockIdx.x * 256 + threadIdx.x;
    const int row = idx >> 5;
    const int c4  = idx & 31;

    const float m0 = g_pm[row], m1 = g_pm[MROWS + row];
    const float l0 = g_pl[row], l1 = g_pl[MROWS + row];
    const float m  = fmaxf(m0, m1);
    const float a0 = __expf(m0 - m);
    const float a1 = __expf(m1 - m);
    const float inv = 1.0f / (a0 * l0 + a1 * l1);

    float4 o0 = *(const float4*)&g_pO[(size_t)row * HEAD + c4 * 4];
    float4 o1 = *(const float4*)&g_pO[(size_t)(MROWS + row) * HEAD + c4 * 4];
    float4 r;
    r.x = (a0 * o0.x + a1 * o1.x) * inv;
    r.y = (a0 * o0.y + a1 * o1.y) * inv;
    r.z = (a0 * o0.z + a1 * o1.z) * inv;
    r.w = (a0 * o0.w + a1 * o1.w) * inv;
    *(float4*)&out[(size_t)row * HEAD + c4 * 4] = r;
}

// ---------------------------------------------------------------------------
extern "C" void kernel_launch(void* const* d_in, const int* in_sizes, int n_in,
                              void* d_out, int out_size)
{
    const float* x  = (const float*)d_in[0];
    const float* Wk = (const float*)d_in[1];
    // d_in[2] = W_query: unused (reference uses key() for q too)
    const float* Wv = (const float*)d_in[3];
    float* out = (float*)d_out;

    wprep_kernel<<<1024, 256>>>(Wk, Wv);

    cudaFuncSetAttribute(proj_mma_kernel, cudaFuncAttributeMaxDynamicSharedMemorySize,
                         PROJ_SMEM);
    dim3 pgrid(128, 2);
    proj_mma_kernel<<<pgrid, 256, PROJ_SMEM>>>(x);

    const int attn_smem = (128 * ASTR * 2 + 128 * SSTR + 3 * 128) * (int)sizeof(float);
    cudaFuncSetAttribute(attn_partial, cudaFuncAttributeMaxDynamicSharedMemorySize, attn_smem);
    attn_partial<<<256, 256, attn_smem>>>();

    merge_kernel<<<(MROWS * 32) / 256, 256>>>(out);
}

// round 9
// speedup vs baseline: 4.1492x; 1.4776x over previous
#include <cuda_runtime.h>
#include <cuda_bf16.h>
#include <stdint.h>

#define BATCH   8
#define SEQ     2048
#define EMBED   1024
#define HEAD    128
#define MROWS   16384
#define TQ      16

// Scratch — __device__ globals, no alloc.
__device__ float g_pO[2 * MROWS * HEAD];
__device__ float g_pm[2 * MROWS];
__device__ float g_pl[2 * MROWS];
// K/V projections stored bf16-split (written by proj epilogue)
__device__ __align__(16) __nv_bfloat16 g_Khi[MROWS * HEAD];
__device__ __align__(16) __nv_bfloat16 g_Klo[MROWS * HEAD];
__device__ __align__(16) __nv_bfloat16 g_Vhi[MROWS * HEAD];
__device__ __align__(16) __nv_bfloat16 g_Vlo[MROWS * HEAD];
// W transposed + bf16-split for proj
__device__ __align__(16) __nv_bfloat16 g_wt_hi[2 * HEAD * EMBED];
__device__ __align__(16) __nv_bfloat16 g_wt_lo[2 * HEAD * EMBED];

// ---------------------------------------------------------------------------
__device__ __forceinline__ uint32_t smem_u32(const void* p) {
    uint32_t a;
    asm("{ .reg .u64 t; cvta.to.shared.u64 t, %1; cvt.u32.u64 %0, t; }"
        : "=r"(a) : "l"(p));
    return a;
}
__device__ __forceinline__ void ldsm_x4(uint32_t* r, uint32_t addr) {
    asm volatile("ldmatrix.sync.aligned.m8n8.x4.shared.b16 {%0,%1,%2,%3}, [%4];"
                 : "=r"(r[0]), "=r"(r[1]), "=r"(r[2]), "=r"(r[3]) : "r"(addr));
}
__device__ __forceinline__ void ldsm_x2(uint32_t* r, uint32_t addr) {
    asm volatile("ldmatrix.sync.aligned.m8n8.x2.shared.b16 {%0,%1}, [%2];"
                 : "=r"(r[0]), "=r"(r[1]) : "r"(addr));
}
__device__ __forceinline__ void ldsm_x2t(uint32_t* r, uint32_t addr) {
    asm volatile("ldmatrix.sync.aligned.m8n8.x2.trans.shared.b16 {%0,%1}, [%2];"
                 : "=r"(r[0]), "=r"(r[1]) : "r"(addr));
}
__device__ __forceinline__ void mma_bf16(float* c, const uint32_t* a, const uint32_t* b) {
    asm volatile(
        "mma.sync.aligned.m16n8k16.row.col.f32.bf16.bf16.f32 "
        "{%0,%1,%2,%3}, {%4,%5,%6,%7}, {%8,%9}, {%0,%1,%2,%3};"
        : "+f"(c[0]), "+f"(c[1]), "+f"(c[2]), "+f"(c[3])
        : "r"(a[0]), "r"(a[1]), "r"(a[2]), "r"(a[3]), "r"(b[0]), "r"(b[1]));
}
__device__ __forceinline__ void split2(float a, float b, uint32_t& hi, uint32_t& lo) {
    __nv_bfloat162 h = __floats2bfloat162_rn(a, b);
    float2 hf = __bfloat1622float2(h);
    __nv_bfloat162 l = __floats2bfloat162_rn(a - hf.x, b - hf.y);
    hi = *(uint32_t*)&h;
    lo = *(uint32_t*)&l;
}

// ---------------------------------------------------------------------------
// W prep: transpose + bf16-split. Wk/Wv are [1024][128].
// ---------------------------------------------------------------------------
__global__ __launch_bounds__(256) void wprep_kernel(
    const float* __restrict__ Wk, const float* __restrict__ Wv)
{
    int idx = blockIdx.x * 256 + threadIdx.x;
    int n = idx & 127;
    int k = (idx >> 7) & 1023;
    int m = idx >> 17;
    float f = (m ? Wv : Wk)[k * HEAD + n];
    __nv_bfloat16 hi = __float2bfloat16(f);
    float rem = f - __bfloat162float(hi);
    __nv_bfloat16 lo = __float2bfloat16(rem);
    size_t o = (size_t)(m * HEAD + n) * EMBED + k;
    g_wt_hi[o] = hi;
    g_wt_lo[o] = lo;
}

// ---------------------------------------------------------------------------
// Projection GEMM via mma.sync bf16 (3-product split).
// Epilogue writes bf16 hi/lo split K/V directly.
// ---------------------------------------------------------------------------
#define PSTR 72
#define TILE_B (128 * PSTR * 2)
#define PROJ_SMEM (4 * TILE_B)

__global__ __launch_bounds__(256) void proj_mma_kernel(const float* __restrict__ x)
{
    extern __shared__ char smem[];
    __nv_bfloat16* Ahi = (__nv_bfloat16*)(smem);
    __nv_bfloat16* Alo = (__nv_bfloat16*)(smem + TILE_B);
    __nv_bfloat16* Bhi = (__nv_bfloat16*)(smem + 2 * TILE_B);
    __nv_bfloat16* Blo = (__nv_bfloat16*)(smem + 3 * TILE_B);
    const uint32_t sAhi = smem_u32(Ahi), sAlo = smem_u32(Alo);
    const uint32_t sBhi = smem_u32(Bhi), sBlo = smem_u32(Blo);

    const int bm  = blockIdx.x;
    const int bn  = blockIdx.y;
    const int tid = threadIdx.x;
    const int wid = tid >> 5;
    const int lane = tid & 31;

    const int warp_m = (wid >> 2) * 64;
    const int warp_n = (wid & 3) * 32;

    const int r = tid >> 1;
    const int h = tid & 1;
    const float* xrow = x + (size_t)(bm * 128 + r) * EMBED;
    const __nv_bfloat16* wh = g_wt_hi + (size_t)(bn * 128 + r) * EMBED;
    const __nv_bfloat16* wl = g_wt_lo + (size_t)(bn * 128 + r) * EMBED;

    const int lg = lane >> 3, lr = lane & 7;
    const int a_row_off = lr + (lg & 1) * 8;
    const int a_col_off = (lg >> 1) * 8;
    const int b_lane = lane & 15;
    const int b_row_off = b_lane & 7;
    const int b_col_off = (b_lane >> 3) * 8;

    float acc[4][4][4] = {};

    for (int c = 0; c < 16; c++) {
        const int k0 = c * 64;
        __syncthreads();
        #pragma unroll
        for (int j = 0; j < 8; j++) {
            float4 f = *(const float4*)&xrow[k0 + h * 32 + j * 4];
            uint2 hi2, lo2;
            split2(f.x, f.y, hi2.x, lo2.x);
            split2(f.z, f.w, hi2.y, lo2.y);
            int off = r * PSTR + h * 32 + j * 4;
            *(uint2*)&Ahi[off] = hi2;
            *(uint2*)&Alo[off] = lo2;
        }
        #pragma unroll
        for (int j = 0; j < 4; j++) {
            int ks = k0 + h * 32 + j * 8;
            int off = r * PSTR + h * 32 + j * 8;
            *(uint4*)&Bhi[off] = *(const uint4*)&wh[ks];
            *(uint4*)&Blo[off] = *(const uint4*)&wl[ks];
        }
        __syncthreads();

        #pragma unroll
        for (int kk4 = 0; kk4 < 4; kk4++) {
            const int kk = kk4 * 16;
            uint32_t ah[4][4], al[4][4], bh[4][2], bl[4][2];
            #pragma unroll
            for (int mf = 0; mf < 4; mf++) {
                uint32_t eo = (uint32_t)((warp_m + mf * 16 + a_row_off) * PSTR
                                         + kk + a_col_off) * 2;
                ldsm_x4(ah[mf], sAhi + eo);
                ldsm_x4(al[mf], sAlo + eo);
            }
            #pragma unroll
            for (int nf = 0; nf < 4; nf++) {
                uint32_t eo = (uint32_t)((warp_n + nf * 8 + b_row_off) * PSTR
                                         + kk + b_col_off) * 2;
                ldsm_x2(bh[nf], sBhi + eo);
                ldsm_x2(bl[nf], sBlo + eo);
            }
            #pragma unroll
            for (int mf = 0; mf < 4; mf++)
                #pragma unroll
                for (int nf = 0; nf < 4; nf++) {
                    mma_bf16(acc[mf][nf], ah[mf], bh[nf]);
                    mma_bf16(acc[mf][nf], ah[mf], bl[nf]);
                    mma_bf16(acc[mf][nf], al[mf], bh[nf]);
                }
        }
    }

    // epilogue: write bf16 hi/lo split
    __nv_bfloat16* dhi = (bn ? g_Vhi : g_Khi) + (size_t)bm * 128 * HEAD;
    __nv_bfloat16* dlo = (bn ? g_Vlo : g_Klo) + (size_t)bm * 128 * HEAD;
    const int frow = lane >> 2;
    const int fcol = (lane & 3) * 2;
    #pragma unroll
    for (int mf = 0; mf < 4; mf++) {
        #pragma unroll
        for (int nf = 0; nf < 4; nf++) {
            int row0 = warp_m + mf * 16 + frow;
            int col  = warp_n + nf * 8 + fcol;
            uint32_t h0, l0, h1, l1;
            split2(acc[mf][nf][0], acc[mf][nf][1], h0, l0);
            split2(acc[mf][nf][2], acc[mf][nf][3], h1, l1);
            *(uint32_t*)&dhi[(size_t)row0 * HEAD + col]       = h0;
            *(uint32_t*)&dlo[(size_t)row0 * HEAD + col]       = l0;
            *(uint32_t*)&dhi[(size_t)(row0 + 8) * HEAD + col] = h1;
            *(uint32_t*)&dlo[(size_t)(row0 + 8) * HEAD + col] = l1;
        }
    }
}

// ---------------------------------------------------------------------------
// Flash-attention partial on mma.sync bf16 (3-product splits everywhere).
// BQ=BK=128, 8 warps x 16 q-rows, register-resident softmax.
// grid = 256 1-D blocks: (qi, b, half) split-K schedule, big tiles first.
// ---------------------------------------------------------------------------
#define KSTR 136     // bf16 smem row stride
#define ATILE (128 * KSTR * 2)          // 34816 bytes
#define ATTN_SMEM (4 * ATILE)           // Qhi,Qlo,KVhi,KVlo = 139264

__global__ __launch_bounds__(256, 1) void attn_partial(void)
{
    const int t    = blockIdx.x;
    const int qi   = (TQ - 1) - (t >> 4);
    const int b    = (t >> 1) & 7;
    const int half = t & 1;
    const int hm   = (qi + 1) >> 1;
    const int jbeg = half ? hm : 0;
    const int jend = half ? (qi + 1) : hm;

    const int tid  = threadIdx.x;
    const int wid  = tid >> 5;
    const int lane = tid & 31;

    const size_t prow0 = (size_t)half * MROWS + (size_t)b * SEQ + qi * 128;
    const size_t pbase = prow0 * HEAD;

    if (jbeg == jend) {
        float4 z = make_float4(0.f, 0.f, 0.f, 0.f);
        #pragma unroll
        for (int i = 0; i < 16; i++)
            *(float4*)&g_pO[pbase + (size_t)(wid * 16 + i) * HEAD + lane * 4] = z;
        if (tid < 128) { g_pm[prow0 + tid] = -1e30f; g_pl[prow0 + tid] = 0.0f; }
        return;
    }

    extern __shared__ char smc[];
    __nv_bfloat16* Qhi  = (__nv_bfloat16*)(smc);
    __nv_bfloat16* Qlo  = (__nv_bfloat16*)(smc + ATILE);
    __nv_bfloat16* KVhi = (__nv_bfloat16*)(smc + 2 * ATILE);
    __nv_bfloat16* KVlo = (__nv_bfloat16*)(smc + 3 * ATILE);
    const uint32_t sQhi = smem_u32(Qhi), sQlo = smem_u32(Qlo);
    const uint32_t sKVhi = smem_u32(KVhi), sKVlo = smem_u32(KVlo);

    // copy-loop mapping
    const int cr = tid >> 1;
    const int ch = tid & 1;

    const size_t batch0 = (size_t)b * SEQ;

    // --- load Q tile (from K projection: q = key(x)) ---
    {
        const __nv_bfloat16* qh = g_Khi + (batch0 + qi * 128 + cr) * HEAD + ch * 64;
        const __nv_bfloat16* ql = g_Klo + (batch0 + qi * 128 + cr) * HEAD + ch * 64;
        #pragma unroll
        for (int i = 0; i < 8; i++) {
            *(uint4*)&Qhi[cr * KSTR + ch * 64 + i * 8] = *(const uint4*)&qh[i * 8];
            *(uint4*)&Qlo[cr * KSTR + ch * 64 + i * 8] = *(const uint4*)&ql[i * 8];
        }
    }

    // fragment lane mappings
    const int lg = lane >> 3, lr = lane & 7;
    const int a_row_off = lr + (lg & 1) * 8;
    const int a_col_off = (lg >> 1) * 8;
    const int b_lane = lane & 15;
    const int b_row_off = b_lane & 7;
    const int b_col_off = (b_lane >> 3) * 8;

    const int warp_m = wid * 16;
    const int frow = lane >> 2;
    const int fc2  = (lane & 3) * 2;

    float o[16][4] = {};
    float m0 = -1e30f, m1 = -1e30f, l0 = 0.f, l1 = 0.f;
    const float sc = 0.08838834764831845f;

    for (int j = jbeg; j < jend; j++) {
        __syncthreads();   // KV buffer free (prev iter PV done; Q store covered on first)
        // --- load K tile ---
        {
            const __nv_bfloat16* kh = g_Khi + (batch0 + j * 128 + cr) * HEAD + ch * 64;
            const __nv_bfloat16* kl = g_Klo + (batch0 + j * 128 + cr) * HEAD + ch * 64;
            #pragma unroll
            for (int i = 0; i < 8; i++) {
                *(uint4*)&KVhi[cr * KSTR + ch * 64 + i * 8] = *(const uint4*)&kh[i * 8];
                *(uint4*)&KVlo[cr * KSTR + ch * 64 + i * 8] = *(const uint4*)&kl[i * 8];
            }
        }
        __syncthreads();

        // --- S = Q K^T ---
        float s[16][4];
        #pragma unroll
        for (int nf = 0; nf < 16; nf++)
            #pragma unroll
            for (int c = 0; c < 4; c++) s[nf][c] = 0.f;

        #pragma unroll 1
        for (int ks = 0; ks < 8; ks++) {
            uint32_t ah[4], al[4];
            uint32_t ao = (uint32_t)((warp_m + a_row_off) * KSTR + ks * 16 + a_col_off) * 2;
            ldsm_x4(ah, sQhi + ao);
            ldsm_x4(al, sQlo + ao);
            #pragma unroll
            for (int nf = 0; nf < 16; nf++) {
                uint32_t bh[2], bl[2];
                uint32_t bo = (uint32_t)((nf * 8 + b_row_off) * KSTR + ks * 16 + b_col_off) * 2;
                ldsm_x2(bh, sKVhi + bo);
                ldsm_x2(bl, sKVlo + bo);
                mma_bf16(s[nf], ah, bh);
                mma_bf16(s[nf], ah, bl);
                mma_bf16(s[nf], al, bh);
            }
        }
        __syncthreads();   // all warps done reading K

        // --- load V tile into KV (overlaps with softmax below) ---
        {
            const __nv_bfloat16* vh = g_Vhi + (batch0 + j * 128 + cr) * HEAD + ch * 64;
            const __nv_bfloat16* vl = g_Vlo + (batch0 + j * 128 + cr) * HEAD + ch * 64;
            #pragma unroll
            for (int i = 0; i < 8; i++) {
                *(uint4*)&KVhi[cr * KSTR + ch * 64 + i * 8] = *(const uint4*)&vh[i * 8];
                *(uint4*)&KVlo[cr * KSTR + ch * 64 + i * 8] = *(const uint4*)&vl[i * 8];
            }
        }

        // --- softmax (registers only) ---
        #pragma unroll
        for (int nf = 0; nf < 16; nf++)
            #pragma unroll
            for (int c = 0; c < 4; c++) s[nf][c] *= sc;

        if (j == qi) {      // causal mask on the diagonal tile
            #pragma unroll
            for (int nf = 0; nf < 16; nf++) {
                int c0 = nf * 8 + fc2;
                int r0 = warp_m + frow;
                if (c0 > r0)     s[nf][0] = -1e30f;
                if (c0 + 1 > r0) s[nf][1] = -1e30f;
                if (c0 > r0 + 8)     s[nf][2] = -1e30f;
                if (c0 + 1 > r0 + 8) s[nf][3] = -1e30f;
            }
        }

        float mx0 = -1e30f, mx1 = -1e30f;
        #pragma unroll
        for (int nf = 0; nf < 16; nf++) {
            mx0 = fmaxf(mx0, fmaxf(s[nf][0], s[nf][1]));
            mx1 = fmaxf(mx1, fmaxf(s[nf][2], s[nf][3]));
        }
        mx0 = fmaxf(mx0, __shfl_xor_sync(0xFFFFFFFFu, mx0, 1));
        mx0 = fmaxf(mx0, __shfl_xor_sync(0xFFFFFFFFu, mx0, 2));
        mx1 = fmaxf(mx1, __shfl_xor_sync(0xFFFFFFFFu, mx1, 1));
        mx1 = fmaxf(mx1, __shfl_xor_sync(0xFFFFFFFFu, mx1, 2));

        float mn0 = fmaxf(m0, mx0);
        float mn1 = fmaxf(m1, mx1);
        float e0 = __expf(m0 - mn0);
        float e1 = __expf(m1 - mn1);
        m0 = mn0; m1 = mn1;

        uint32_t ph01[16], ph23[16], pl01[16], pl23[16];
        float sum0 = 0.f, sum1 = 0.f;
        #pragma unroll
        for (int nf = 0; nf < 16; nf++) {
            float p0 = __expf(s[nf][0] - mn0);
            float p1 = __expf(s[nf][1] - mn0);
            float p2 = __expf(s[nf][2] - mn1);
            float p3 = __expf(s[nf][3] - mn1);
            sum0 += p0 + p1;
            sum1 += p2 + p3;
            split2(p0, p1, ph01[nf], pl01[nf]);
            split2(p2, p3, ph23[nf], pl23[nf]);
        }
        sum0 += __shfl_xor_sync(0xFFFFFFFFu, sum0, 1);
        sum0 += __shfl_xor_sync(0xFFFFFFFFu, sum0, 2);
        sum1 += __shfl_xor_sync(0xFFFFFFFFu, sum1, 1);
        sum1 += __shfl_xor_sync(0xFFFFFFFFu, sum1, 2);
        l0 = l0 * e0 + sum0;
        l1 = l1 * e1 + sum1;

        #pragma unroll
        for (int nf = 0; nf < 16; nf++) {
            o[nf][0] *= e0; o[nf][1] *= e0;
            o[nf][2] *= e1; o[nf][3] *= e1;
        }
        __syncthreads();   // V visible

        // --- O += P V ---
        #pragma unroll
        for (int ks = 0; ks < 8; ks++) {
            uint32_t ah[4] = {ph01[2 * ks], ph23[2 * ks], ph01[2 * ks + 1], ph23[2 * ks + 1]};
            uint32_t al[4] = {pl01[2 * ks], pl23[2 * ks], pl01[2 * ks + 1], pl23[2 * ks + 1]};
            #pragma unroll
            for (int nf = 0; nf < 16; nf++) {
                uint32_t bh[2], bl[2];
                uint32_t bo = (uint32_t)((ks * 16 + b_lane) * KSTR + nf * 8) * 2;
                ldsm_x2t(bh, sKVhi + bo);
                ldsm_x2t(bl, sKVlo + bo);
                mma_bf16(o[nf], ah, bh);
                mma_bf16(o[nf], ah, bl);
                mma_bf16(o[nf], al, bh);
            }
        }
    }

    // --- write partials ---
    const int r0 = warp_m + frow;
    const int r1 = r0 + 8;
    #pragma unroll
    for (int nf = 0; nf < 16; nf++) {
        *(float2*)&g_pO[pbase + (size_t)r0 * HEAD + nf * 8 + fc2] =
            make_float2(o[nf][0], o[nf][1]);
        *(float2*)&g_pO[pbase + (size_t)r1 * HEAD + nf * 8 + fc2] =
            make_float2(o[nf][2], o[nf][3]);
    }
    if ((lane & 3) == 0) {
        g_pm[prow0 + r0] = m0;
        g_pl[prow0 + r0] = l0;
        g_pm[prow0 + r1] = m1;
        g_pl[prow0 + r1] = l1;
    }
}

// ---------------------------------------------------------------------------
__global__ __launch_bounds__(256) void merge_kernel(float* __restrict__ out)
{
    const int idx = blockIdx.x * 256 + threadIdx.x;
    const int row = idx >> 5;
    const int c4  = idx & 31;

    const float m0 = g_pm[row], m1 = g_pm[MROWS + row];
    const float l0 = g_pl[row], l1 = g_pl[MROWS + row];
    const float m  = fmaxf(m0, m1);
    const float a0 = __expf(m0 - m);
    const float a1 = __expf(m1 - m);
    const float inv = 1.0f / (a0 * l0 + a1 * l1);

    float4 o0 = *(const float4*)&g_pO[(size_t)row * HEAD + c4 * 4];
    float4 o1 = *(const float4*)&g_pO[(size_t)(MROWS + row) * HEAD + c4 * 4];
    float4 r;
    r.x = (a0 * o0.x + a1 * o1.x) * inv;
    r.y = (a0 * o0.y + a1 * o1.y) * inv;
    r.z = (a0 * o0.z + a1 * o1.z) * inv;
    r.w = (a0 * o0.w + a1 * o1.w) * inv;
    *(float4*)&out[(size_t)row * HEAD + c4 * 4] = r;
}

// ---------------------------------------------------------------------------
extern "C" void kernel_launch(void* const* d_in, const int* in_sizes, int n_in,
                              void* d_out, int out_size)
{
    const float* x  = (const float*)d_in[0];
    const float* Wk = (const float*)d_in[1];
    // d_in[2] = W_query: unused (reference uses key() for q too)
    const float* Wv = (const float*)d_in[3];
    float* out = (float*)d_out;

    wprep_kernel<<<1024, 256>>>(Wk, Wv);

    cudaFuncSetAttribute(proj_mma_kernel, cudaFuncAttributeMaxDynamicSharedMemorySize,
                         PROJ_SMEM);
    dim3 pgrid(128, 2);
    proj_mma_kernel<<<pgrid, 256, PROJ_SMEM>>>(x);

    cudaFuncSetAttribute(attn_partial, cudaFuncAttributeMaxDynamicSharedMemorySize,
                         ATTN_SMEM);
    attn_partial<<<256, 256, ATTN_SMEM>>>();

    merge_kernel<<<(MROWS * 32) / 256, 256>>>(out);
}